// round 12
// baseline (speedup 1.0000x reference)
#include <cuda_runtime.h>
#include <cuda_fp16.h>
#include <stdint.h>

#define N_TOK   32768
#define N_CODE  8192
#define DIM     256
#define QUANT_ELEMS (N_TOK * DIM)

// ---------------- static scratch ----------------
// fp16 2-limb fragment-packed operands (m16n8k16 register order).
// g_xs: [blk16 (2048)][kstep (16)][limb (2)][lane (32)][4 x b32] = 33.6 MB
// g_es: [blk8  (1024)][kstep (16)][limb (2)][lane (32)][2 x b32] =  8.4 MB
__device__ uint32_t g_xs[(size_t)2048 * 16 * 2 * 128];
__device__ uint32_t g_es[(size_t)1024 * 16 * 2 * 64];
__device__ float g_e2[N_CODE];
__device__ int   g_idx[N_TOK];
__device__ int   g_c1[N_TOK];
__device__ int   g_c2[N_TOK];
__device__ float g_part[4096];

// ---------------- helpers ----------------
__device__ __forceinline__ uint32_t smem_u32(const void* p) {
    uint32_t a;
    asm("{ .reg .u64 t; cvta.to.shared.u64 t, %1; cvt.u32.u64 %0, t; }"
        : "=r"(a) : "l"(p));
    return a;
}
__device__ __forceinline__ void cp16(uint32_t dst, const void* src) {
    asm volatile("cp.async.cg.shared.global [%0], [%1], 16;" :: "r"(dst), "l"(src));
}
#define CP_COMMIT() asm volatile("cp.async.commit_group;" ::: "memory")
#define CP_WAIT(n)  asm volatile("cp.async.wait_group %0;" :: "n"(n) : "memory")

// exact 2-limb fp16 split: x = h + m + O(2^-22 x); subtraction exact
__device__ __forceinline__ void split2h(float x, uint16_t& hb, uint16_t& mb) {
    __half hh = __float2half_rn(x);
    float  hf = __half2float(hh);
    __half mm = __float2half_rn(x - hf);
    hb = __half_as_ushort(hh);
    mb = __half_as_ushort(mm);
}
__device__ __forceinline__ uint32_t hpack(uint16_t lo, uint16_t hi) {
    return (uint32_t)lo | ((uint32_t)hi << 16);
}

// m16n8k16 fp16 mma, D += A*B (row.col), fp32 accumulate in place
__device__ __forceinline__ void mma16(float* c, const uint4& a, const uint2& b) {
    asm volatile(
        "mma.sync.aligned.m16n8k16.row.col.f32.f16.f16.f32 "
        "{%0,%1,%2,%3}, {%4,%5,%6,%7}, {%8,%9}, {%0,%1,%2,%3};"
        : "+f"(c[0]), "+f"(c[1]), "+f"(c[2]), "+f"(c[3])
        : "r"(a.x), "r"(a.y), "r"(a.z), "r"(a.w), "r"(b.x), "r"(b.y));
}

// ---------------- prep kernels (validated round 11) ----------------
__global__ void k_prep_x(const float* __restrict__ X) {
    int gt   = blockIdx.x * 256 + threadIdx.x;
    int lane = gt & 31;
    int w    = gt >> 5;
    int ks   = w & 15;
    int blk  = w >> 4;
    int g = lane >> 2, t = lane & 3;
    const float* r0 = X + (blk * 16 + g) * DIM + ks * 16 + 2 * t;
    const float* r1 = r0 + 8 * DIM;
    float s[8] = { r0[0], r0[1], r1[0], r1[1], r0[8], r0[9], r1[8], r1[9] };
    uint16_t h[8], m[8];
#pragma unroll
    for (int i = 0; i < 8; i++) split2h(s[i], h[i], m[i]);
    uint32_t* base = g_xs + (size_t)(blk * 16 + ks) * 256 + lane * 4;
    *(uint4*)(base)       = make_uint4(hpack(h[0],h[1]), hpack(h[2],h[3]),
                                       hpack(h[4],h[5]), hpack(h[6],h[7]));
    *(uint4*)(base + 128) = make_uint4(hpack(m[0],m[1]), hpack(m[2],m[3]),
                                       hpack(m[4],m[5]), hpack(m[6],m[7]));
}

__global__ void k_prep_e(const float* __restrict__ E) {
    int gt   = blockIdx.x * 256 + threadIdx.x;
    int lane = gt & 31;
    int w    = gt >> 5;
    int ks   = w & 15;
    int blk  = w >> 4;
    int g = lane >> 2, t = lane & 3;
    const float* r = E + (blk * 8 + g) * DIM + ks * 16 + 2 * t;
    float s[4] = { r[0], r[1], r[8], r[9] };
    uint16_t h[4], m[4];
#pragma unroll
    for (int i = 0; i < 4; i++) split2h(s[i], h[i], m[i]);
    uint32_t* base = g_es + (size_t)(blk * 16 + ks) * 128 + lane * 2;
    *(uint2*)(base)      = make_uint2(hpack(h[0],h[1]), hpack(h[2],h[3]));
    *(uint2*)(base + 64) = make_uint2(hpack(m[0],m[1]), hpack(m[2],m[3]));
}

__global__ void k_e2(const float* __restrict__ E) {
    int warp = (blockIdx.x << 3) + (threadIdx.x >> 5);
    int lane = threadIdx.x & 31;
    const float* row = E + warp * DIM;
    float s = 0.f;
#pragma unroll
    for (int i = 0; i < 8; i++) { float v = row[lane + i * 32]; s = fmaf(v, v, s); }
#pragma unroll
    for (int off = 16; off; off >>= 1) s += __shfl_down_sync(0xffffffffu, s, off);
    if (lane == 0) g_e2[warp] = s;
}

// ---------------- main: fp16 3-pass mma GEMM, B reg-pipelined, top-2 argmin --
// 256 CTAs x 512 threads (4 m-warps x 4 n-warps, warp tile 32x32).
// A slab (128 KB) SMEM-resident; B via __ldg prefetched ONE kstep ahead into
// a register double-buffer — LDG->HMMA distance = one full MMA batch.
#define A_BYTES   131072
#define SM_MIN1   A_BYTES
#define SM_MIN2   (A_BYTES + 1024)
#define SM_TOTAL  (A_BYTES + 2048)

__device__ __forceinline__ unsigned long long packdi(float v, int i) {
    uint32_t u = __float_as_uint(v);
    u = (u & 0x80000000u) ? ~u : (u | 0x80000000u);
    return ((unsigned long long)u << 32) | (unsigned)i;
}

__global__ __launch_bounds__(512, 1) void k_main() {
    extern __shared__ __align__(16) char sm[];
    unsigned long long* s_min1 = (unsigned long long*)(sm + SM_MIN1);
    unsigned long long* s_min2 = (unsigned long long*)(sm + SM_MIN2);

    const int tid  = threadIdx.x;
    const int lane = tid & 31, wid = tid >> 5;
    const int wm = wid & 3, wn = wid >> 2;       // 4 x 4 warp grid
    const int g = lane >> 2, t = lane & 3;
    const int m0 = blockIdx.x * 128;
    const uint32_t sb = smem_u32(sm);

    if (tid < 128) { s_min1[tid] = ~0ull; s_min2[tid] = ~0ull; }

    const char* gA = (const char*)g_xs + (size_t)blockIdx.x * A_BYTES;

    // A slab: one-shot cp.async load, single barrier
#pragma unroll
    for (int i = 0; i < 16; i++) {
        int off = (tid + i * 512) * 16;
        cp16(sb + off, gA + off);
    }
    CP_COMMIT();
    CP_WAIT(0);
    __syncthreads();

    // per-token-row top-2 (4 rows per thread)
    float v1[4], v2[4];
    int   i1[4], i2[4];
#pragma unroll
    for (int i = 0; i < 4; i++) { v1[i] = v2[i] = 3.4e38f; i1[i] = i2[i] = 0; }

    const uint32_t* gBlane = g_es + (size_t)lane * 2;
    const int nbBase = wn * 4;                   // warp's code sub-block

    // register double-buffer for B fragments
    uint2 bf[2][2][4];                           // [buf][limb][nf]
    // prefetch c = 0  (nt=0, ks=0)
#pragma unroll
    for (int nf = 0; nf < 4; nf++) {
        const uint32_t* pb = gBlane + (size_t)((nbBase + nf) * 16) * 128;
        bf[0][0][nf] = __ldg((const uint2*)pb);
        bf[0][1][nf] = __ldg((const uint2*)(pb + 64));
    }

    float cacc[2][4][4];

    for (int c = 0; c < 1024; c++) {             // 64 n-tiles x 16 ksteps
        const int nt = c >> 4, ks = c & 15, buf = c & 1;

        // prefetch B for iteration c+1 into the other register buffer
        if (c + 1 < 1024) {
            const int c2 = c + 1, nt2 = c2 >> 4, ks2 = c2 & 15;
#pragma unroll
            for (int nf = 0; nf < 4; nf++) {
                const uint32_t* pb =
                    gBlane + (size_t)((nt2 * 16 + nbBase + nf) * 16 + ks2) * 128;
                bf[buf ^ 1][0][nf] = __ldg((const uint2*)pb);
                bf[buf ^ 1][1][nf] = __ldg((const uint2*)(pb + 64));
            }
        }

        if (ks == 0) {
#pragma unroll
            for (int mf = 0; mf < 2; mf++)
#pragma unroll
                for (int nf = 0; nf < 4; nf++)
#pragma unroll
                    for (int e = 0; e < 4; e++) cacc[mf][nf][e] = 0.f;
        }

        // A fragments from resident SMEM
        uint4 af[2][2];
#pragma unroll
        for (int ap = 0; ap < 2; ap++)
#pragma unroll
            for (int mf = 0; mf < 2; mf++)
                af[ap][mf] = *(const uint4*)(sm + (wm * 2 + mf) * 16384 +
                                             ks * 1024 + ap * 512 + lane * 16);
        // 3 limb passes: hh, hm, mh (drop mm ~ 2^-22)
#pragma unroll
        for (int ap = 0; ap < 2; ap++)
#pragma unroll
            for (int bp = 0; bp < 2; bp++) {
                if (ap + bp < 2) {
#pragma unroll
                    for (int nf = 0; nf < 4; nf++)
#pragma unroll
                        for (int mf = 0; mf < 2; mf++)
                            mma16(cacc[mf][nf], af[ap][mf], bf[buf][bp][nf]);
                }
            }

        if (ks == 15) {
            // distance epilogue + per-thread running TOP-2 (ascending codes)
            const float* e2t = g_e2 + nt * 128 + wn * 32;
#pragma unroll
            for (int nf = 0; nf < 4; nf++) {
                float2 e2v = *(const float2*)(e2t + nf * 8 + 2 * t);
                int code = nt * 128 + wn * 32 + nf * 8 + 2 * t;
#pragma unroll
                for (int mf = 0; mf < 2; mf++) {
#pragma unroll
                    for (int h = 0; h < 2; h++) {
                        int tk = mf * 2 + h;
                        float d0 = fmaf(-2.f, cacc[mf][nf][h * 2 + 0], e2v.x);
                        float d1 = fmaf(-2.f, cacc[mf][nf][h * 2 + 1], e2v.y);
                        if (d0 < v1[tk]) { v2[tk]=v1[tk]; i2[tk]=i1[tk]; v1[tk]=d0; i1[tk]=code; }
                        else if (d0 < v2[tk]) { v2[tk]=d0; i2[tk]=code; }
                        if (d1 < v1[tk]) { v2[tk]=v1[tk]; i2[tk]=i1[tk]; v1[tk]=d1; i1[tk]=code+1; }
                        else if (d1 < v2[tk]) { v2[tk]=d1; i2[tk]=code+1; }
                    }
                }
            }
        }
    }

    // quad-shfl top-2 set merge, then two-phase smem atomicMin
#pragma unroll
    for (int tk = 0; tk < 4; tk++) {
        unsigned long long p1 = packdi(v1[tk], i1[tk]);
        unsigned long long p2 = packdi(v2[tk], i2[tk]);
#pragma unroll
        for (int off = 1; off <= 2; off <<= 1) {
            unsigned long long q1 = __shfl_xor_sync(0xffffffffu, p1, off);
            unsigned long long q2 = __shfl_xor_sync(0xffffffffu, p2, off);
            unsigned long long lo = p1 < q1 ? p1 : q1;
            unsigned long long hi = p1 < q1 ? q1 : p1;
            unsigned long long m2 = p2 < q2 ? p2 : q2;
            p1 = lo;
            p2 = hi < m2 ? hi : m2;
        }
        if (t == 0) {
            int mf = tk >> 1, h = tk & 1;
            int slot = wm * 32 + mf * 16 + g + h * 8;
            atomicMin(&s_min1[slot], p1);
        }
        __syncthreads();
        if (t == 0) {
            int mf = tk >> 1, h = tk & 1;
            int slot = wm * 32 + mf * 16 + g + h * 8;
            unsigned long long g1 = s_min1[slot];
            unsigned long long cand = (p1 == g1) ? p2 : p1;
            atomicMin(&s_min2[slot], cand);
        }
        __syncthreads();
    }

    if (tid < 128) {
        g_c1[m0 + tid] = (int)(s_min1[tid] & 0xffffffffu);
        g_c2[m0 + tid] = (int)(s_min2[tid] & 0xffffffffu);
    }
}

// ---------------- exact fp32 rescore of the two candidates ----------------
__global__ void k_pick(const float* __restrict__ X, const float* __restrict__ E,
                       float* __restrict__ out_idx_f) {
    int warp = blockIdx.x * 8 + (threadIdx.x >> 5);   // one warp per token
    int lane = threadIdx.x & 31;
    int c1 = g_c1[warp], c2 = g_c2[warp];
    const float* x  = X + (size_t)warp * DIM;
    const float* e1 = E + (size_t)c1 * DIM;
    const float* e2 = E + (size_t)c2 * DIM;
    float dot1 = 0.f, dot2 = 0.f;
#pragma unroll
    for (int i = 0; i < 8; i++) {
        int k = lane + i * 32;
        float xv = x[k];
        dot1 = fmaf(xv, e1[k], dot1);
        dot2 = fmaf(xv, e2[k], dot2);
    }
#pragma unroll
    for (int off = 16; off; off >>= 1) {
        dot1 += __shfl_down_sync(0xffffffffu, dot1, off);
        dot2 += __shfl_down_sync(0xffffffffu, dot2, off);
    }
    if (lane == 0) {
        float d1 = fmaf(-2.f, dot1, g_e2[c1]);
        float d2 = fmaf(-2.f, dot2, g_e2[c2]);
        int c = (d2 < d1 || (d2 == d1 && c2 < c1)) ? c2 : c1;
        g_idx[warp] = c;
        out_idx_f[warp] = (float)c;
    }
}

// ---------------- gather + loss (validated) ----------------
__global__ void k_gather(const float* __restrict__ X, const float* __restrict__ E,
                         float* __restrict__ outq) {
    __shared__ float red[256];
    const int tid = threadIdx.x;
    const long base = (long)blockIdx.x * 2048;
    float s = 0.f;
#pragma unroll
    for (int i = 0; i < 8; i++) {
        long e = base + i * 256 + tid;
        int  m = (int)(e >> 8);
        int  d = (int)(e & 255);
        float q = E[g_idx[m] * DIM + d];
        float x = X[e];
        float diff = q - x;
        outq[e] = x + diff;
        s = fmaf(diff, diff, s);
    }
    red[tid] = s;
    __syncthreads();
#pragma unroll
    for (int st = 128; st; st >>= 1) {
        if (tid < st) red[tid] += red[tid + st];
        __syncthreads();
    }
    if (tid == 0) g_part[blockIdx.x] = red[0];
}
__global__ void k_loss(float* __restrict__ loss_out) {
    __shared__ float red[256];
    const int tid = threadIdx.x;
    float s = 0.f;
    for (int i = tid; i < 4096; i += 256) s += g_part[i];
    red[tid] = s;
    __syncthreads();
#pragma unroll
    for (int st = 128; st; st >>= 1) {
        if (tid < st) red[tid] += red[tid + st];
        __syncthreads();
    }
    if (tid == 0) loss_out[0] = 2.0f * (red[0] / (float)QUANT_ELEMS);
}

// ---------------- launch ----------------
extern "C" void kernel_launch(void* const* d_in, const int* in_sizes, int n_in,
                              void* d_out, int out_size) {
    const float* X = (const float*)d_in[0];
    const float* E = (const float*)d_in[1];
    float* out = (float*)d_out;

    float* outq    = out;
    float* outloss = out + QUANT_ELEMS;
    float* outidx  = out + QUANT_ELEMS + 1;

    cudaFuncSetAttribute(k_main, cudaFuncAttributeMaxDynamicSharedMemorySize,
                         SM_TOTAL);

    k_prep_x<<<4096, 256>>>(X);
    k_prep_e<<<2048, 256>>>(E);
    k_e2    <<<N_CODE / 8, 256>>>(E);
    k_main  <<<N_TOK / 128, 512, SM_TOTAL>>>();
    k_pick  <<<N_TOK / 8, 256>>>(X, E, outidx);
    k_gather<<<QUANT_ELEMS / 2048, 256>>>(X, E, outq);
    k_loss  <<<1, 256>>>(outloss);

    (void)in_sizes; (void)n_in; (void)out_size;
}

// round 13
// speedup vs baseline: 1.4726x; 1.4726x over previous
#include <cuda_runtime.h>
#include <cuda_fp16.h>
#include <stdint.h>

#define N_TOK   32768
#define N_CODE  8192
#define DIM     256
#define QUANT_ELEMS (N_TOK * DIM)

// ---------------- static scratch ----------------
// fp16 2-limb fragment-packed operands (m16n8k16 register order).
// g_xs: [blk16 (2048)][kstep (16)][limb (2)][lane (32)][4 x b32] = 33.6 MB
// g_es: [blk8  (1024)][kstep (16)][limb (2)][lane (32)][2 x b32] =  8.4 MB
__device__ uint32_t g_xs[(size_t)2048 * 16 * 2 * 128];
__device__ uint32_t g_es[(size_t)1024 * 16 * 2 * 64];
__device__ float g_e2[N_CODE];
__device__ int   g_idx[N_TOK];
__device__ int   g_c1[N_TOK];
__device__ int   g_c2[N_TOK];
__device__ float g_part[4096];

// ---------------- helpers ----------------
__device__ __forceinline__ uint32_t smem_u32(const void* p) {
    uint32_t a;
    asm("{ .reg .u64 t; cvta.to.shared.u64 t, %1; cvt.u32.u64 %0, t; }"
        : "=r"(a) : "l"(p));
    return a;
}
__device__ __forceinline__ void cp16(uint32_t dst, const void* src) {
    asm volatile("cp.async.cg.shared.global [%0], [%1], 16;" :: "r"(dst), "l"(src));
}
#define CP_COMMIT() asm volatile("cp.async.commit_group;" ::: "memory")
#define CP_WAIT(n)  asm volatile("cp.async.wait_group %0;" :: "n"(n) : "memory")

// exact 2-limb fp16 split: x = h + m + O(2^-22 x); subtraction exact
__device__ __forceinline__ void split2h(float x, uint16_t& hb, uint16_t& mb) {
    __half hh = __float2half_rn(x);
    float  hf = __half2float(hh);
    __half mm = __float2half_rn(x - hf);
    hb = __half_as_ushort(hh);
    mb = __half_as_ushort(mm);
}
__device__ __forceinline__ uint32_t hpack(uint16_t lo, uint16_t hi) {
    return (uint32_t)lo | ((uint32_t)hi << 16);
}

// m16n8k16 fp16 mma, D += A*B (row.col), fp32 accumulate in place
__device__ __forceinline__ void mma16(float* c, const uint4& a, const uint2& b) {
    asm volatile(
        "mma.sync.aligned.m16n8k16.row.col.f32.f16.f16.f32 "
        "{%0,%1,%2,%3}, {%4,%5,%6,%7}, {%8,%9}, {%0,%1,%2,%3};"
        : "+f"(c[0]), "+f"(c[1]), "+f"(c[2]), "+f"(c[3])
        : "r"(a.x), "r"(a.y), "r"(a.z), "r"(a.w), "r"(b.x), "r"(b.y));
}

// ---------------- prep kernels (validated round 11) ----------------
__global__ void k_prep_x(const float* __restrict__ X) {
    int gt   = blockIdx.x * 256 + threadIdx.x;
    int lane = gt & 31;
    int w    = gt >> 5;
    int ks   = w & 15;
    int blk  = w >> 4;
    int g = lane >> 2, t = lane & 3;
    const float* r0 = X + (blk * 16 + g) * DIM + ks * 16 + 2 * t;
    const float* r1 = r0 + 8 * DIM;
    float s[8] = { r0[0], r0[1], r1[0], r1[1], r0[8], r0[9], r1[8], r1[9] };
    uint16_t h[8], m[8];
#pragma unroll
    for (int i = 0; i < 8; i++) split2h(s[i], h[i], m[i]);
    uint32_t* base = g_xs + (size_t)(blk * 16 + ks) * 256 + lane * 4;
    *(uint4*)(base)       = make_uint4(hpack(h[0],h[1]), hpack(h[2],h[3]),
                                       hpack(h[4],h[5]), hpack(h[6],h[7]));
    *(uint4*)(base + 128) = make_uint4(hpack(m[0],m[1]), hpack(m[2],m[3]),
                                       hpack(m[4],m[5]), hpack(m[6],m[7]));
}

__global__ void k_prep_e(const float* __restrict__ E) {
    int gt   = blockIdx.x * 256 + threadIdx.x;
    int lane = gt & 31;
    int w    = gt >> 5;
    int ks   = w & 15;
    int blk  = w >> 4;
    int g = lane >> 2, t = lane & 3;
    const float* r = E + (blk * 8 + g) * DIM + ks * 16 + 2 * t;
    float s[4] = { r[0], r[1], r[8], r[9] };
    uint16_t h[4], m[4];
#pragma unroll
    for (int i = 0; i < 4; i++) split2h(s[i], h[i], m[i]);
    uint32_t* base = g_es + (size_t)(blk * 16 + ks) * 128 + lane * 2;
    *(uint2*)(base)      = make_uint2(hpack(h[0],h[1]), hpack(h[2],h[3]));
    *(uint2*)(base + 64) = make_uint2(hpack(m[0],m[1]), hpack(m[2],m[3]));
}

__global__ void k_e2(const float* __restrict__ E) {
    int warp = (blockIdx.x << 3) + (threadIdx.x >> 5);
    int lane = threadIdx.x & 31;
    const float* row = E + warp * DIM;
    float s = 0.f;
#pragma unroll
    for (int i = 0; i < 8; i++) { float v = row[lane + i * 32]; s = fmaf(v, v, s); }
#pragma unroll
    for (int off = 16; off; off >>= 1) s += __shfl_down_sync(0xffffffffu, s, off);
    if (lane == 0) g_e2[warp] = s;
}

// ---------------- main: fp16 3-pass mma GEMM, reg-pipelined (named bufs) ----
// 256 CTAs x 512 threads (4 m-warps x 4 n-warps, warp tile 32x32).
// A slab (128 KB) SMEM-resident; B prefetched one iteration ahead into
// STATICALLY-NAMED register sets bfA/bfB (2x-unrolled loop -> no spills).
#define A_BYTES   131072
#define SM_MIN1   A_BYTES
#define SM_MIN2   (A_BYTES + 1024)
#define SM_TOTAL  (A_BYTES + 2048)

__device__ __forceinline__ unsigned long long packdi(float v, int i) {
    uint32_t u = __float_as_uint(v);
    u = (u & 0x80000000u) ? ~u : (u | 0x80000000u);
    return ((unsigned long long)u << 32) | (unsigned)i;
}

// prefetch B fragments for flat iteration c into bf (static after inlining)
__device__ __forceinline__ void prefB(uint2 bf[2][4], const uint32_t* gBlane,
                                      int nbBase, int c) {
    const int nt = c >> 4, ks = c & 15;
#pragma unroll
    for (int nf = 0; nf < 4; nf++) {
        const uint32_t* pb =
            gBlane + (size_t)((nt * 16 + nbBase + nf) * 16 + ks) * 128;
        bf[0][nf] = __ldg((const uint2*)pb);
        bf[1][nf] = __ldg((const uint2*)(pb + 64));
    }
}

// one kstep of compute for flat iteration c, consuming bf
__device__ __forceinline__ void bodyC(int c, const uint2 bf[2][4],
                                      const char* sm_, int wm, int wn,
                                      int lane, int t,
                                      float cacc[2][4][4],
                                      float v1[4], float v2[4],
                                      int i1[4], int i2[4]) {
    const int nt = c >> 4, ks = c & 15;

    if (ks == 0) {
#pragma unroll
        for (int mf = 0; mf < 2; mf++)
#pragma unroll
            for (int nf = 0; nf < 4; nf++)
#pragma unroll
                for (int e = 0; e < 4; e++) cacc[mf][nf][e] = 0.f;
    }

    // A fragments from resident SMEM
    uint4 af[2][2];
#pragma unroll
    for (int ap = 0; ap < 2; ap++)
#pragma unroll
        for (int mf = 0; mf < 2; mf++)
            af[ap][mf] = *(const uint4*)(sm_ + (wm * 2 + mf) * 16384 +
                                         ks * 1024 + ap * 512 + lane * 16);
    // 3 limb passes: hh, hm, mh (drop mm ~ 2^-22)
#pragma unroll
    for (int ap = 0; ap < 2; ap++)
#pragma unroll
        for (int bp = 0; bp < 2; bp++) {
            if (ap + bp < 2) {
#pragma unroll
                for (int nf = 0; nf < 4; nf++)
#pragma unroll
                    for (int mf = 0; mf < 2; mf++)
                        mma16(cacc[mf][nf], af[ap][mf], bf[bp][nf]);
            }
        }

    if (ks == 15) {
        // distance epilogue + per-thread running TOP-2 (ascending codes)
        const float* e2t = g_e2 + nt * 128 + wn * 32;
#pragma unroll
        for (int nf = 0; nf < 4; nf++) {
            float2 e2v = *(const float2*)(e2t + nf * 8 + 2 * t);
            int code = nt * 128 + wn * 32 + nf * 8 + 2 * t;
#pragma unroll
            for (int mf = 0; mf < 2; mf++) {
#pragma unroll
                for (int h = 0; h < 2; h++) {
                    int tk = mf * 2 + h;
                    float d0 = fmaf(-2.f, cacc[mf][nf][h * 2 + 0], e2v.x);
                    float d1 = fmaf(-2.f, cacc[mf][nf][h * 2 + 1], e2v.y);
                    if (d0 < v1[tk]) { v2[tk]=v1[tk]; i2[tk]=i1[tk]; v1[tk]=d0; i1[tk]=code; }
                    else if (d0 < v2[tk]) { v2[tk]=d0; i2[tk]=code; }
                    if (d1 < v1[tk]) { v2[tk]=v1[tk]; i2[tk]=i1[tk]; v1[tk]=d1; i1[tk]=code+1; }
                    else if (d1 < v2[tk]) { v2[tk]=d1; i2[tk]=code+1; }
                }
            }
        }
    }
}

__global__ __launch_bounds__(512, 1) void k_main() {
    extern __shared__ __align__(16) char sm[];
    unsigned long long* s_min1 = (unsigned long long*)(sm + SM_MIN1);
    unsigned long long* s_min2 = (unsigned long long*)(sm + SM_MIN2);

    const int tid  = threadIdx.x;
    const int lane = tid & 31, wid = tid >> 5;
    const int wm = wid & 3, wn = wid >> 2;       // 4 x 4 warp grid
    const int g = lane >> 2, t = lane & 3;
    const int m0 = blockIdx.x * 128;
    const uint32_t sb = smem_u32(sm);

    if (tid < 128) { s_min1[tid] = ~0ull; s_min2[tid] = ~0ull; }

    const char* gA = (const char*)g_xs + (size_t)blockIdx.x * A_BYTES;

    // A slab: one-shot cp.async load, single barrier
#pragma unroll
    for (int i = 0; i < 16; i++) {
        int off = (tid + i * 512) * 16;
        cp16(sb + off, gA + off);
    }
    CP_COMMIT();
    CP_WAIT(0);
    __syncthreads();

    // per-token-row top-2 (4 rows per thread)
    float v1[4], v2[4];
    int   i1[4], i2[4];
#pragma unroll
    for (int i = 0; i < 4; i++) { v1[i] = v2[i] = 3.4e38f; i1[i] = i2[i] = 0; }

    const uint32_t* gBlane = g_es + (size_t)lane * 2;
    const int nbBase = wn * 4;

    float cacc[2][4][4];
    uint2 bfA[2][4], bfB[2][4];                  // named double buffers

    prefB(bfA, gBlane, nbBase, 0);

    for (int cc = 0; cc < 512; cc++) {           // 2x-unrolled flat loop
        const int c0 = 2 * cc, c1 = c0 + 1;
        prefB(bfB, gBlane, nbBase, c1);
        bodyC(c0, bfA, sm, wm, wn, lane, t, cacc, v1, v2, i1, i2);
        if (cc + 1 < 512) prefB(bfA, gBlane, nbBase, c1 + 1);
        bodyC(c1, bfB, sm, wm, wn, lane, t, cacc, v1, v2, i1, i2);
    }

    // quad-shfl top-2 set merge, then two-phase smem atomicMin
#pragma unroll
    for (int tk = 0; tk < 4; tk++) {
        unsigned long long p1 = packdi(v1[tk], i1[tk]);
        unsigned long long p2 = packdi(v2[tk], i2[tk]);
#pragma unroll
        for (int off = 1; off <= 2; off <<= 1) {
            unsigned long long q1 = __shfl_xor_sync(0xffffffffu, p1, off);
            unsigned long long q2 = __shfl_xor_sync(0xffffffffu, p2, off);
            unsigned long long lo = p1 < q1 ? p1 : q1;
            unsigned long long hi = p1 < q1 ? q1 : p1;
            unsigned long long m2 = p2 < q2 ? p2 : q2;
            p1 = lo;
            p2 = hi < m2 ? hi : m2;
        }
        if (t == 0) {
            int mf = tk >> 1, h = tk & 1;
            int slot = wm * 32 + mf * 16 + g + h * 8;
            atomicMin(&s_min1[slot], p1);
        }
        __syncthreads();
        if (t == 0) {
            int mf = tk >> 1, h = tk & 1;
            int slot = wm * 32 + mf * 16 + g + h * 8;
            unsigned long long g1 = s_min1[slot];
            unsigned long long cand = (p1 == g1) ? p2 : p1;
            atomicMin(&s_min2[slot], cand);
        }
        __syncthreads();
    }

    if (tid < 128) {
        g_c1[m0 + tid] = (int)(s_min1[tid] & 0xffffffffu);
        g_c2[m0 + tid] = (int)(s_min2[tid] & 0xffffffffu);
    }
}

// ---------------- exact fp32 rescore of the two candidates ----------------
__global__ void k_pick(const float* __restrict__ X, const float* __restrict__ E,
                       float* __restrict__ out_idx_f) {
    int warp = blockIdx.x * 8 + (threadIdx.x >> 5);   // one warp per token
    int lane = threadIdx.x & 31;
    int c1 = g_c1[warp], c2 = g_c2[warp];
    const float* x  = X + (size_t)warp * DIM;
    const float* e1 = E + (size_t)c1 * DIM;
    const float* e2 = E + (size_t)c2 * DIM;
    float dot1 = 0.f, dot2 = 0.f;
#pragma unroll
    for (int i = 0; i < 8; i++) {
        int k = lane + i * 32;
        float xv = x[k];
        dot1 = fmaf(xv, e1[k], dot1);
        dot2 = fmaf(xv, e2[k], dot2);
    }
#pragma unroll
    for (int off = 16; off; off >>= 1) {
        dot1 += __shfl_down_sync(0xffffffffu, dot1, off);
        dot2 += __shfl_down_sync(0xffffffffu, dot2, off);
    }
    if (lane == 0) {
        float d1 = fmaf(-2.f, dot1, g_e2[c1]);
        float d2 = fmaf(-2.f, dot2, g_e2[c2]);
        int c = (d2 < d1 || (d2 == d1 && c2 < c1)) ? c2 : c1;
        g_idx[warp] = c;
        out_idx_f[warp] = (float)c;
    }
}

// ---------------- gather + loss (validated) ----------------
__global__ void k_gather(const float* __restrict__ X, const float* __restrict__ E,
                         float* __restrict__ outq) {
    __shared__ float red[256];
    const int tid = threadIdx.x;
    const long base = (long)blockIdx.x * 2048;
    float s = 0.f;
#pragma unroll
    for (int i = 0; i < 8; i++) {
        long e = base + i * 256 + tid;
        int  m = (int)(e >> 8);
        int  d = (int)(e & 255);
        float q = E[g_idx[m] * DIM + d];
        float x = X[e];
        float diff = q - x;
        outq[e] = x + diff;
        s = fmaf(diff, diff, s);
    }
    red[tid] = s;
    __syncthreads();
#pragma unroll
    for (int st = 128; st; st >>= 1) {
        if (tid < st) red[tid] += red[tid + st];
        __syncthreads();
    }
    if (tid == 0) g_part[blockIdx.x] = red[0];
}
__global__ void k_loss(float* __restrict__ loss_out) {
    __shared__ float red[256];
    const int tid = threadIdx.x;
    float s = 0.f;
    for (int i = tid; i < 4096; i += 256) s += g_part[i];
    red[tid] = s;
    __syncthreads();
#pragma unroll
    for (int st = 128; st; st >>= 1) {
        if (tid < st) red[tid] += red[tid + st];
        __syncthreads();
    }
    if (tid == 0) loss_out[0] = 2.0f * (red[0] / (float)QUANT_ELEMS);
}

// ---------------- launch ----------------
extern "C" void kernel_launch(void* const* d_in, const int* in_sizes, int n_in,
                              void* d_out, int out_size) {
    const float* X = (const float*)d_in[0];
    const float* E = (const float*)d_in[1];
    float* out = (float*)d_out;

    float* outq    = out;
    float* outloss = out + QUANT_ELEMS;
    float* outidx  = out + QUANT_ELEMS + 1;

    cudaFuncSetAttribute(k_main, cudaFuncAttributeMaxDynamicSharedMemorySize,
                         SM_TOTAL);

    k_prep_x<<<4096, 256>>>(X);
    k_prep_e<<<2048, 256>>>(E);
    k_e2    <<<N_CODE / 8, 256>>>(E);
    k_main  <<<N_TOK / 128, 512, SM_TOTAL>>>();
    k_pick  <<<N_TOK / 8, 256>>>(X, E, outidx);
    k_gather<<<QUANT_ELEMS / 2048, 256>>>(X, E, outq);
    k_loss  <<<1, 256>>>(outloss);

    (void)in_sizes; (void)n_in; (void)out_size;
}

// round 14
// speedup vs baseline: 2.4708x; 1.6778x over previous
#include <cuda_runtime.h>
#include <cuda_fp16.h>
#include <stdint.h>

#define N_TOK   32768
#define N_CODE  8192
#define DIM     256
#define QUANT_ELEMS (N_TOK * DIM)

// ---------------- static scratch ----------------
// fp16 h-limb fragment-packed operands (m16n8k16 register order).
// g_xs: [blk16 (2048)][kstep (16)][lane (32)][4 x b32] = 16.8 MB
// g_es: [blk8  (1024)][kstep (16)][lane (32)][2 x b32] =  4.2 MB
__device__ uint32_t g_xs[(size_t)2048 * 16 * 128];
__device__ uint32_t g_es[(size_t)1024 * 16 * 64];
__device__ float g_e2[N_CODE];
__device__ int   g_idx[N_TOK];
__device__ int   g_cand[(size_t)N_TOK * 32];      // 32 candidates per token
__device__ unsigned long long g_best[N_TOK];
__device__ float g_part[4096];

// ---------------- helpers ----------------
__device__ __forceinline__ uint32_t smem_u32(const void* p) {
    uint32_t a;
    asm("{ .reg .u64 t; cvta.to.shared.u64 t, %1; cvt.u32.u64 %0, t; }"
        : "=r"(a) : "l"(p));
    return a;
}
__device__ __forceinline__ void cp16(uint32_t dst, const void* src) {
    asm volatile("cp.async.cg.shared.global [%0], [%1], 16;" :: "r"(dst), "l"(src));
}
#define CP_COMMIT() asm volatile("cp.async.commit_group;" ::: "memory")
#define CP_WAIT(n)  asm volatile("cp.async.wait_group %0;" :: "n"(n) : "memory")

__device__ __forceinline__ uint32_t hpack2(float a, float b) {
    __half2 h2 = __floats2half2_rn(a, b);
    return *(uint32_t*)&h2;
}

// m16n8k16 fp16 mma, D += A*B (row.col), fp32 accumulate in place
__device__ __forceinline__ void mma16(float* c, const uint4& a, const uint2& b) {
    asm volatile(
        "mma.sync.aligned.m16n8k16.row.col.f32.f16.f16.f32 "
        "{%0,%1,%2,%3}, {%4,%5,%6,%7}, {%8,%9}, {%0,%1,%2,%3};"
        : "+f"(c[0]), "+f"(c[1]), "+f"(c[2]), "+f"(c[3])
        : "r"(a.x), "r"(a.y), "r"(a.z), "r"(a.w), "r"(b.x), "r"(b.y));
}

__device__ __forceinline__ unsigned long long packdi(float v, int i) {
    uint32_t u = __float_as_uint(v);
    u = (u & 0x80000000u) ? ~u : (u | 0x80000000u);
    return ((unsigned long long)u << 32) | (unsigned)i;
}

// ---------------- prep kernels ----------------
__global__ void k_prep_x(const float* __restrict__ X) {
    int gt   = blockIdx.x * 256 + threadIdx.x;   // 1,048,576 threads
    if (gt < N_TOK) g_best[gt] = ~0ull;          // init rescore slots
    int lane = gt & 31;
    int w    = gt >> 5;
    int ks   = w & 15;
    int blk  = w >> 4;
    int g = lane >> 2, t = lane & 3;
    const float* r0 = X + (blk * 16 + g) * DIM + ks * 16 + 2 * t;
    const float* r1 = r0 + 8 * DIM;
    uint32_t* base = g_xs + (size_t)(blk * 16 + ks) * 128 + lane * 4;
    *(uint4*)base = make_uint4(hpack2(r0[0], r0[1]), hpack2(r1[0], r1[1]),
                               hpack2(r0[8], r0[9]), hpack2(r1[8], r1[9]));
}

__global__ void k_prep_e(const float* __restrict__ E) {
    int gt   = blockIdx.x * 256 + threadIdx.x;   // 524,288 threads
    int lane = gt & 31;
    int w    = gt >> 5;
    int ks   = w & 15;
    int blk  = w >> 4;
    int g = lane >> 2, t = lane & 3;
    const float* r = E + (blk * 8 + g) * DIM + ks * 16 + 2 * t;
    uint32_t* base = g_es + (size_t)(blk * 16 + ks) * 64 + lane * 2;
    *(uint2*)base = make_uint2(hpack2(r[0], r[1]), hpack2(r[8], r[9]));
}

__global__ void k_e2(const float* __restrict__ E) {
    int warp = (blockIdx.x << 3) + (threadIdx.x >> 5);
    int lane = threadIdx.x & 31;
    const float* row = E + warp * DIM;
    float s = 0.f;
#pragma unroll
    for (int i = 0; i < 8; i++) { float v = row[lane + i * 32]; s = fmaf(v, v, s); }
#pragma unroll
    for (int off = 16; off; off >>= 1) s += __shfl_down_sync(0xffffffffu, s, off);
    if (lane == 0) g_e2[warp] = s;
}

// ---------------- main: fp16 1-pass (hh) mma + per-thread top-2 -------------
// 256 CTAs x 512 threads (4 m-warps x 4 n-warps, warp tile 32x32).
// A h-slab (64 KB) SMEM-resident; B h-fragments via __ldg, prefetch distance 3
// through four statically-named register buffers. No block-wide merge: each
// thread emits its top-2 candidates; k_pick2 rescored all 32/token in fp32.
#define A_BYTES 65536

__device__ __forceinline__ void prefB(uint2 bf[4], const uint32_t* gBlane,
                                      int nbBase, int c) {
    if (c < 1024) {
        const int nt = c >> 4, ks = c & 15;
#pragma unroll
        for (int nf = 0; nf < 4; nf++) {
            const uint32_t* pb =
                gBlane + (size_t)((nt * 16 + nbBase + nf) * 16 + ks) * 64;
            bf[nf] = __ldg((const uint2*)pb);
        }
    }
}

__device__ __forceinline__ void bodyC(int c, const uint2 bf[4],
                                      const char* sm_, int wm, int wn,
                                      int lane, int t,
                                      float cacc[2][4][4],
                                      float v1[4], float v2[4],
                                      int i1[4], int i2[4]) {
    const int nt = c >> 4, ks = c & 15;

    if (ks == 0) {
#pragma unroll
        for (int mf = 0; mf < 2; mf++)
#pragma unroll
            for (int nf = 0; nf < 4; nf++)
#pragma unroll
                for (int e = 0; e < 4; e++) cacc[mf][nf][e] = 0.f;
    }

    uint4 af[2];
#pragma unroll
    for (int mf = 0; mf < 2; mf++)
        af[mf] = *(const uint4*)(sm_ + (wm * 2 + mf) * 8192 +
                                 ks * 512 + lane * 16);
#pragma unroll
    for (int nf = 0; nf < 4; nf++)
#pragma unroll
        for (int mf = 0; mf < 2; mf++)
            mma16(cacc[mf][nf], af[mf], bf[nf]);

    if (ks == 15) {
        const float* e2t = g_e2 + nt * 128 + wn * 32;
#pragma unroll
        for (int nf = 0; nf < 4; nf++) {
            float2 e2v = *(const float2*)(e2t + nf * 8 + 2 * t);
            int code = nt * 128 + wn * 32 + nf * 8 + 2 * t;
#pragma unroll
            for (int mf = 0; mf < 2; mf++) {
#pragma unroll
                for (int h = 0; h < 2; h++) {
                    int tk = mf * 2 + h;
                    float d0 = fmaf(-2.f, cacc[mf][nf][h * 2 + 0], e2v.x);
                    float d1 = fmaf(-2.f, cacc[mf][nf][h * 2 + 1], e2v.y);
                    if (d0 < v1[tk]) { v2[tk]=v1[tk]; i2[tk]=i1[tk]; v1[tk]=d0; i1[tk]=code; }
                    else if (d0 < v2[tk]) { v2[tk]=d0; i2[tk]=code; }
                    if (d1 < v1[tk]) { v2[tk]=v1[tk]; i2[tk]=i1[tk]; v1[tk]=d1; i1[tk]=code+1; }
                    else if (d1 < v2[tk]) { v2[tk]=d1; i2[tk]=code+1; }
                }
            }
        }
    }
}

__global__ __launch_bounds__(512, 1) void k_main() {
    extern __shared__ __align__(16) char sm[];

    const int tid  = threadIdx.x;
    const int lane = tid & 31, wid = tid >> 5;
    const int wm = wid & 3, wn = wid >> 2;       // 4 x 4 warp grid
    const int g = lane >> 2, t = lane & 3;
    const int m0 = blockIdx.x * 128;
    const uint32_t sb = smem_u32(sm);

    const char* gA = (const char*)g_xs + (size_t)blockIdx.x * A_BYTES;

    // A h-slab: one-shot cp.async load, single barrier
#pragma unroll
    for (int i = 0; i < 8; i++) {
        int off = (tid + i * 512) * 16;
        cp16(sb + off, gA + off);
    }
    CP_COMMIT();
    CP_WAIT(0);
    __syncthreads();

    float v1[4], v2[4];
    int   i1[4], i2[4];
#pragma unroll
    for (int i = 0; i < 4; i++) { v1[i] = v2[i] = 3.4e38f; i1[i] = i2[i] = 0; }

    const uint32_t* gBlane = g_es + (size_t)lane * 2;
    const int nbBase = wn * 4;

    float cacc[2][4][4];
    uint2 b0[4], b1[4], b2[4], b3[4];            // named ring, distance 3

    prefB(b0, gBlane, nbBase, 0);
    prefB(b1, gBlane, nbBase, 1);
    prefB(b2, gBlane, nbBase, 2);

    for (int cc = 0; cc < 256; cc++) {           // 4x-unrolled flat loop
        const int c = 4 * cc;
        prefB(b3, gBlane, nbBase, c + 3);
        bodyC(c + 0, b0, sm, wm, wn, lane, t, cacc, v1, v2, i1, i2);
        prefB(b0, gBlane, nbBase, c + 4);
        bodyC(c + 1, b1, sm, wm, wn, lane, t, cacc, v1, v2, i1, i2);
        prefB(b1, gBlane, nbBase, c + 5);
        bodyC(c + 2, b2, sm, wm, wn, lane, t, cacc, v1, v2, i1, i2);
        prefB(b2, gBlane, nbBase, c + 6);
        bodyC(c + 3, b3, sm, wm, wn, lane, t, cacc, v1, v2, i1, i2);
    }

    // emit per-thread top-2 candidates (no merge)
    const int slot = (wn * 4 + t) * 2;
#pragma unroll
    for (int tk = 0; tk < 4; tk++) {
        int token = m0 + wm * 32 + (tk >> 1) * 16 + g + (tk & 1) * 8;
        g_cand[(size_t)token * 32 + slot]     = i1[tk];
        g_cand[(size_t)token * 32 + slot + 1] = i2[tk];
    }
}

// ---------------- exact fp32 rescore of all 32 candidates ----------------
__global__ void k_pick2(const float* __restrict__ X, const float* __restrict__ E) {
    int W    = blockIdx.x * 8 + (threadIdx.x >> 5);   // global warp id
    int lane = threadIdx.x & 31;
    int token = W >> 5;
    int c = g_cand[W];                                // W == token*32 + cand
    const float* x = X + (size_t)token * DIM;
    const float* e = E + (size_t)c * DIM;
    float dot = 0.f;
#pragma unroll
    for (int i = 0; i < 8; i++) {
        int k = lane + i * 32;
        dot = fmaf(x[k], e[k], dot);
    }
#pragma unroll
    for (int off = 16; off; off >>= 1)
        dot += __shfl_down_sync(0xffffffffu, dot, off);
    if (lane == 0) {
        float d = fmaf(-2.f, dot, g_e2[c]);
        atomicMin(&g_best[token], packdi(d, c));
    }
}

__global__ void k_fin(float* __restrict__ out_idx_f) {
    int token = blockIdx.x * 256 + threadIdx.x;
    int idx = (int)(g_best[token] & 0xffffffffu);
    g_idx[token] = idx;
    out_idx_f[token] = (float)idx;
}

// ---------------- gather + loss (validated) ----------------
__global__ void k_gather(const float* __restrict__ X, const float* __restrict__ E,
                         float* __restrict__ outq) {
    __shared__ float red[256];
    const int tid = threadIdx.x;
    const long base = (long)blockIdx.x * 2048;
    float s = 0.f;
#pragma unroll
    for (int i = 0; i < 8; i++) {
        long e = base + i * 256 + tid;
        int  m = (int)(e >> 8);
        int  d = (int)(e & 255);
        float q = E[g_idx[m] * DIM + d];
        float x = X[e];
        float diff = q - x;
        outq[e] = x + diff;
        s = fmaf(diff, diff, s);
    }
    red[tid] = s;
    __syncthreads();
#pragma unroll
    for (int st = 128; st; st >>= 1) {
        if (tid < st) red[tid] += red[tid + st];
        __syncthreads();
    }
    if (tid == 0) g_part[blockIdx.x] = red[0];
}
__global__ void k_loss(float* __restrict__ loss_out) {
    __shared__ float red[256];
    const int tid = threadIdx.x;
    float s = 0.f;
    for (int i = tid; i < 4096; i += 256) s += g_part[i];
    red[tid] = s;
    __syncthreads();
#pragma unroll
    for (int st = 128; st; st >>= 1) {
        if (tid < st) red[tid] += red[tid + st];
        __syncthreads();
    }
    if (tid == 0) loss_out[0] = 2.0f * (red[0] / (float)QUANT_ELEMS);
}

// ---------------- launch ----------------
extern "C" void kernel_launch(void* const* d_in, const int* in_sizes, int n_in,
                              void* d_out, int out_size) {
    const float* X = (const float*)d_in[0];
    const float* E = (const float*)d_in[1];
    float* out = (float*)d_out;

    float* outq    = out;
    float* outloss = out + QUANT_ELEMS;
    float* outidx  = out + QUANT_ELEMS + 1;

    cudaFuncSetAttribute(k_main, cudaFuncAttributeMaxDynamicSharedMemorySize,
                         A_BYTES);

    k_prep_x<<<4096, 256>>>(X);
    k_prep_e<<<2048, 256>>>(E);
    k_e2    <<<N_CODE / 8, 256>>>(E);
    k_main  <<<N_TOK / 128, 512, A_BYTES>>>();
    k_pick2 <<<(N_TOK * 32) / 8, 256>>>(X, E);
    k_fin   <<<N_TOK / 256, 256>>>(outidx);
    k_gather<<<QUANT_ELEMS / 2048, 256>>>(X, E, outq);
    k_loss  <<<1, 256>>>(outloss);

    (void)in_sizes; (void)n_in; (void)out_size;
}

// round 16
// speedup vs baseline: 2.8554x; 1.1557x over previous
#include <cuda_runtime.h>
#include <cuda_fp16.h>
#include <stdint.h>

#define N_TOK   32768
#define N_CODE  8192
#define DIM     256
#define QUANT_ELEMS (N_TOK * DIM)

// ---------------- static scratch ----------------
// fp16 h-limb fragment-packed operands (m16n8k16 register order).
// g_xs: [blk16 (2048)][kstep (16)][lane (32)][4 x b32] = 16.8 MB
// g_es: [blk8  (1024)][kstep (16)][lane (32)][2 x b32] =  4.2 MB (+pad for
//        the one-tile-ahead prefetch overrun at nt=63)
__device__ uint32_t g_xs[(size_t)2048 * 16 * 128];
__device__ uint32_t g_es[(size_t)1024 * 16 * 64 + 20480];
__device__ float g_e2[N_CODE];
__device__ int   g_idx[N_TOK];
__device__ int   g_cand[(size_t)N_TOK * 32];      // 32 candidates per token
__device__ unsigned long long g_best[N_TOK];
__device__ float g_part[4096];

// ---------------- helpers ----------------
__device__ __forceinline__ uint32_t smem_u32(const void* p) {
    uint32_t a;
    asm("{ .reg .u64 t; cvta.to.shared.u64 t, %1; cvt.u32.u64 %0, t; }"
        : "=r"(a) : "l"(p));
    return a;
}
__device__ __forceinline__ void cp16(uint32_t dst, const void* src) {
    asm volatile("cp.async.cg.shared.global [%0], [%1], 16;" :: "r"(dst), "l"(src));
}
#define CP_COMMIT() asm volatile("cp.async.commit_group;" ::: "memory")
#define CP_WAIT(n)  asm volatile("cp.async.wait_group %0;" :: "n"(n) : "memory")

__device__ __forceinline__ uint32_t hpack2(float a, float b) {
    __half2 h2 = __floats2half2_rn(a, b);
    return *(uint32_t*)&h2;
}

// m16n8k16 fp16 mma, D += A*B (row.col), fp32 accumulate in place
__device__ __forceinline__ void mma16(float* c, const uint4& a, const uint2& b) {
    asm volatile(
        "mma.sync.aligned.m16n8k16.row.col.f32.f16.f16.f32 "
        "{%0,%1,%2,%3}, {%4,%5,%6,%7}, {%8,%9}, {%0,%1,%2,%3};"
        : "+f"(c[0]), "+f"(c[1]), "+f"(c[2]), "+f"(c[3])
        : "r"(a.x), "r"(a.y), "r"(a.z), "r"(a.w), "r"(b.x), "r"(b.y));
}

__device__ __forceinline__ unsigned long long packdi(float v, int i) {
    uint32_t u = __float_as_uint(v);
    u = (u & 0x80000000u) ? ~u : (u | 0x80000000u);
    return ((unsigned long long)u << 32) | (unsigned)i;
}

// ---------------- prep kernels (validated round 14) ----------------
__global__ void k_prep_x(const float* __restrict__ X) {
    int gt   = blockIdx.x * 256 + threadIdx.x;
    if (gt < N_TOK) g_best[gt] = ~0ull;          // init rescore slots
    int lane = gt & 31;
    int w    = gt >> 5;
    int ks   = w & 15;
    int blk  = w >> 4;
    int g = lane >> 2, t = lane & 3;
    const float* r0 = X + (blk * 16 + g) * DIM + ks * 16 + 2 * t;
    const float* r1 = r0 + 8 * DIM;
    uint32_t* base = g_xs + (size_t)(blk * 16 + ks) * 128 + lane * 4;
    *(uint4*)base = make_uint4(hpack2(r0[0], r0[1]), hpack2(r1[0], r1[1]),
                               hpack2(r0[8], r0[9]), hpack2(r1[8], r1[9]));
}

__global__ void k_prep_e(const float* __restrict__ E) {
    int gt   = blockIdx.x * 256 + threadIdx.x;
    int lane = gt & 31;
    int w    = gt >> 5;
    int ks   = w & 15;
    int blk  = w >> 4;
    int g = lane >> 2, t = lane & 3;
    const float* r = E + (blk * 8 + g) * DIM + ks * 16 + 2 * t;
    uint32_t* base = g_es + (size_t)(blk * 16 + ks) * 64 + lane * 2;
    *(uint2*)base = make_uint2(hpack2(r[0], r[1]), hpack2(r[8], r[9]));
}

__global__ void k_e2(const float* __restrict__ E) {
    int warp = (blockIdx.x << 3) + (threadIdx.x >> 5);
    int lane = threadIdx.x & 31;
    const float* row = E + warp * DIM;
    float s = 0.f;
#pragma unroll
    for (int i = 0; i < 8; i++) { float v = row[lane + i * 32]; s = fmaf(v, v, s); }
#pragma unroll
    for (int off = 16; off; off >>= 1) s += __shfl_down_sync(0xffffffffu, s, off);
    if (lane == 0) g_e2[warp] = s;
}

// ---------------- main: fp16 1-pass mma, tile-unrolled, immediate offsets ---
// 256 CTAs x 512 threads (4 m-warps x 4 n-warps, warp tile 32x32).
// 16-kstep tile fully unrolled: all LDG/LDS offsets and ring indices are
// compile-time immediates; B pointers advance once per tile.
#define A_BYTES 65536

__global__ __launch_bounds__(512, 1) void k_main() {
    extern __shared__ __align__(16) char sm[];

    const int tid  = threadIdx.x;
    const int lane = tid & 31, wid = tid >> 5;
    const int wm = wid & 3, wn = wid >> 2;       // 4 x 4 warp grid
    const int g = lane >> 2, t = lane & 3;
    const int m0 = blockIdx.x * 128;
    const uint32_t sb = smem_u32(sm);

    const char* gA = (const char*)g_xs + (size_t)blockIdx.x * A_BYTES;

    // A h-slab: one-shot cp.async load, single barrier
#pragma unroll
    for (int i = 0; i < 8; i++) {
        int off = (tid + i * 512) * 16;
        cp16(sb + off, gA + off);
    }
    CP_COMMIT();
    CP_WAIT(0);
    __syncthreads();

    float v1[4], v2[4];
    int   i1[4], i2[4];
#pragma unroll
    for (int i = 0; i < 4; i++) { v1[i] = v2[i] = 3.4e38f; i1[i] = i2[i] = 0; }

    const int nbBase = wn * 4;
    // per-nf running B byte pointers (advance +65536 per tile)
    const char* pB[4];
#pragma unroll
    for (int nf = 0; nf < 4; nf++)
        pB[nf] = (const char*)g_es + (size_t)(nbBase + nf) * 16 * 256 + lane * 8;

    // A base pointer: loads at pA + mf*8192 + j*512 (all immediates)
    const char* pA = sm + (wm * 2) * 8192 + lane * 16;

    // ring of 4 statically-indexed B buffers; preload ksteps 0..2
    uint2 bf[4][4];
#pragma unroll
    for (int j = 0; j < 3; j++)
#pragma unroll
        for (int nf = 0; nf < 4; nf++)
            bf[j][nf] = __ldg((const uint2*)(pB[nf] + j * 256));

    float cacc[2][4][4];

    for (int nt = 0; nt < 64; nt++) {
#pragma unroll
        for (int j = 0; j < 16; j++) {
            if (j == 0) {
#pragma unroll
                for (int mf = 0; mf < 2; mf++)
#pragma unroll
                    for (int nf = 0; nf < 4; nf++)
#pragma unroll
                        for (int e = 0; e < 4; e++) cacc[mf][nf][e] = 0.f;
            }

            // prefetch kstep j+3 (next tile when j >= 13) — immediate offsets
            {
                const int off = (j + 3 < 16) ? (j + 3) * 256
                                             : 65536 + (j - 13) * 256;
#pragma unroll
                for (int nf = 0; nf < 4; nf++)
                    bf[(j + 3) & 3][nf] = __ldg((const uint2*)(pB[nf] + off));
            }

            // A fragments (immediate LDS offsets)
            uint4 af0 = *(const uint4*)(pA + j * 512);
            uint4 af1 = *(const uint4*)(pA + 8192 + j * 512);

#pragma unroll
            for (int nf = 0; nf < 4; nf++) {
                mma16(cacc[0][nf], af0, bf[j & 3][nf]);
                mma16(cacc[1][nf], af1, bf[j & 3][nf]);
            }

            if (j == 15) {
                // distance epilogue + per-thread running TOP-2
                const float* e2t = g_e2 + nt * 128 + wn * 32;
#pragma unroll
                for (int nf = 0; nf < 4; nf++) {
                    float2 e2v = __ldg((const float2*)(e2t + nf * 8 + 2 * t));
                    int code = nt * 128 + wn * 32 + nf * 8 + 2 * t;
#pragma unroll
                    for (int mf = 0; mf < 2; mf++) {
#pragma unroll
                        for (int h = 0; h < 2; h++) {
                            int tk = mf * 2 + h;
                            float d0 = fmaf(-2.f, cacc[mf][nf][h * 2 + 0], e2v.x);
                            float d1 = fmaf(-2.f, cacc[mf][nf][h * 2 + 1], e2v.y);
                            if (d0 < v1[tk]) { v2[tk]=v1[tk]; i2[tk]=i1[tk]; v1[tk]=d0; i1[tk]=code; }
                            else if (d0 < v2[tk]) { v2[tk]=d0; i2[tk]=code; }
                            if (d1 < v1[tk]) { v2[tk]=v1[tk]; i2[tk]=i1[tk]; v1[tk]=d1; i1[tk]=code+1; }
                            else if (d1 < v2[tk]) { v2[tk]=d1; i2[tk]=code+1; }
                        }
                    }
                }
            }
        }
#pragma unroll
        for (int nf = 0; nf < 4; nf++) pB[nf] += 65536;
    }

    // emit per-thread top-2 candidates (no merge)
    const int slot = (wn * 4 + t) * 2;
#pragma unroll
    for (int tk = 0; tk < 4; tk++) {
        int token = m0 + wm * 32 + (tk >> 1) * 16 + g + (tk & 1) * 8;
        g_cand[(size_t)token * 32 + slot]     = i1[tk];
        g_cand[(size_t)token * 32 + slot + 1] = i2[tk];
    }
}

// ---------------- exact fp32 rescore of all 32 candidates ----------------
__global__ void k_pick2(const float* __restrict__ X, const float* __restrict__ E) {
    int W    = blockIdx.x * 8 + (threadIdx.x >> 5);   // global warp id
    int lane = threadIdx.x & 31;
    int token = W >> 5;
    int c = g_cand[W];                                // W == token*32 + cand
    const float* x = X + (size_t)token * DIM;
    const float* e = E + (size_t)c * DIM;
    float dot = 0.f;
#pragma unroll
    for (int i = 0; i < 8; i++) {
        int k = lane + i * 32;
        dot = fmaf(x[k], e[k], dot);
    }
#pragma unroll
    for (int off = 16; off; off >>= 1)
        dot += __shfl_down_sync(0xffffffffu, dot, off);
    if (lane == 0) {
        float d = fmaf(-2.f, dot, g_e2[c]);
        atomicMin(&g_best[token], packdi(d, c));
    }
}

__global__ void k_fin(float* __restrict__ out_idx_f) {
    int token = blockIdx.x * 256 + threadIdx.x;
    int idx = (int)(g_best[token] & 0xffffffffu);
    g_idx[token] = idx;
    out_idx_f[token] = (float)idx;
}

// ---------------- gather + loss (validated) ----------------
__global__ void k_gather(const float* __restrict__ X, const float* __restrict__ E,
                         float* __restrict__ outq) {
    __shared__ float red[256];
    const int tid = threadIdx.x;
    const long base = (long)blockIdx.x * 2048;
    float s = 0.f;
#pragma unroll
    for (int i = 0; i < 8; i++) {
        long e = base + i * 256 + tid;
        int  m = (int)(e >> 8);
        int  d = (int)(e & 255);
        float q = E[g_idx[m] * DIM + d];
        float x = X[e];
        float diff = q - x;
        outq[e] = x + diff;
        s = fmaf(diff, diff, s);
    }
    red[tid] = s;
    __syncthreads();
#pragma unroll
    for (int st = 128; st; st >>= 1) {
        if (tid < st) red[tid] += red[tid + st];
        __syncthreads();
    }
    if (tid == 0) g_part[blockIdx.x] = red[0];
}
__global__ void k_loss(float* __restrict__ loss_out) {
    __shared__ float red[256];
    const int tid = threadIdx.x;
    float s = 0.f;
    for (int i = tid; i < 4096; i += 256) s += g_part[i];
    red[tid] = s;
    __syncthreads();
#pragma unroll
    for (int st = 128; st; st >>= 1) {
        if (tid < st) red[tid] += red[tid + st];
        __syncthreads();
    }
    if (tid == 0) loss_out[0] = 2.0f * (red[0] / (float)QUANT_ELEMS);
}

// ---------------- launch ----------------
extern "C" void kernel_launch(void* const* d_in, const int* in_sizes, int n_in,
                              void* d_out, int out_size) {
    const float* X = (const float*)d_in[0];
    const float* E = (const float*)d_in[1];
    float* out = (float*)d_out;

    float* outq    = out;
    float* outloss = out + QUANT_ELEMS;
    float* outidx  = out + QUANT_ELEMS + 1;

    cudaFuncSetAttribute(k_main, cudaFuncAttributeMaxDynamicSharedMemorySize,
                         A_BYTES);

    k_prep_x<<<4096, 256>>>(X);
    k_prep_e<<<2048, 256>>>(E);
    k_e2    <<<N_CODE / 8, 256>>>(E);
    k_main  <<<N_TOK / 128, 512, A_BYTES>>>();
    k_pick2 <<<(N_TOK * 32) / 8, 256>>>(X, E);
    k_fin   <<<N_TOK / 256, 256>>>(outidx);
    k_gather<<<QUANT_ELEMS / 2048, 256>>>(X, E, outq);
    k_loss  <<<1, 256>>>(outloss);

    (void)in_sizes; (void)n_in; (void)out_size;
}